// round 3
// baseline (speedup 1.0000x reference)
#include <cuda_runtime.h>
#include <math.h>

#define Nn 4096
#define Ee 8192
#define Mm 128
#define ND 128
#define ED 64
#define PQ 16
#define LAYERS 4
#define TAU 0.25f
#define FRIC 0.1f

#define NB 64
#define BT 512
#define NT (NB*BT)
#define NW (NT/32)
#define MAXD 32

// ---------------- device scratch (no allocation allowed) ----------------
__device__ float g_a[Nn], g_c[Nn], g_avt[Nn], g_avu[Nn];
__device__ int   g_mol[Nn];
__device__ int   g_cnt[Nn];          // zero at init; reset at end of every launch
__device__ int   g_adj[Nn * MAXD];   // packed (edge<<12)|other
__device__ float g_w[Ee];
__device__ float g_p[Nn * PQ], g_q[Nn * PQ], g_psum[Nn * PQ], g_qsum[Nn * PQ];
__device__ float g_pdot[Nn], g_qdot[Nn];
__device__ float g_su[Nn], g_st[Nn];
__device__ float g_Gm[Mm], g_Sm[Mm], g_h[Mm], g_d[Mm];
__device__ float g_S[LAYERS];
__device__ float g_cTot;
__device__ unsigned g_arrive;        // monotonic grid-barrier counter

__device__ __forceinline__ float warp_sum(float v) {
#pragma unroll
    for (int o = 16; o; o >>= 1) v += __shfl_xor_sync(0xffffffffu, v, o);
    return v;
}
__device__ __forceinline__ float sigmoidf(float x) { return 1.f / (1.f + expf(-x)); }
__device__ __forceinline__ float softplusf(float x) { return fmaxf(x, 0.f) + log1pf(expf(-fabsf(x))); }

// Grid-wide barrier: monotonic counter, no reset needed (each launch consumes
// exactly 11*NB increments; invariant g_arrive % NB == 0 at every entry).
__device__ __forceinline__ void gsync() {
    __threadfence();           // release: my writes visible GPU-wide
    __syncthreads();
    if (threadIdx.x == 0) {
        unsigned t = atomicAdd(&g_arrive, 1u);
        unsigned target = (t / NB + 1u) * NB;
        while (*((volatile unsigned*)&g_arrive) < target) __nanosleep(40);
    }
    __syncthreads();
    __threadfence();           // acquire: invalidate stale L1 before next reads
}

__global__ void __launch_bounds__(BT, 1)
fused_kernel(const float* __restrict__ vf, const float* __restrict__ ef,
             const int* __restrict__ us, const int* __restrict__ vs,
             const float* __restrict__ mnm,
             const float* __restrict__ We, const float* __restrict__ be,
             const float* __restrict__ Wp, const float* __restrict__ bp,
             const float* __restrict__ Wq, const float* __restrict__ bq,
             const float* __restrict__ Wt, const float* __restrict__ Wu,
             float* __restrict__ out)
{
    const int tid  = threadIdx.x;
    const int b    = blockIdx.x;
    const int gtid = b * BT + tid;
    const int wid  = gtid >> 5;
    const int lane = gtid & 31;

    // second-half weight vectors (Wt2, Wu2) + their Gram scalars
    float wt2[PQ], wu2[PQ];
    float nWt = 0.f, nWu = 0.f, dTU = 0.f;
#pragma unroll
    for (int k = 0; k < PQ; k++) {
        wt2[k] = Wt[ND + k]; wu2[k] = Wu[ND + k];
        nWt += wt2[k] * wt2[k]; nWu += wu2[k] * wu2[k]; dTU += wt2[k] * wu2[k];
    }

    // ================= P0: init, mol ids, adjacency fill, node dots, p0 =================
    if (gtid == 0) g_cTot = 0.f;
    if (gtid < LAYERS) g_S[gtid] = 0.f;
    if (gtid < Mm) { g_Gm[gtid] = 0.f; g_Sm[gtid] = 0.f; g_h[gtid] = 0.f; g_d[gtid] = 0.f; }

    // molecule ids: coalesced sweep of mnm (row-major [Mm, Nn])
    for (int idx = gtid; idx < Mm * Nn; idx += NT)
        if (mnm[idx] > 0.5f) g_mol[idx & (Nn - 1)] = idx >> 12;

    // incidence lists
    for (int e = gtid; e < Ee; e += NT) {
        int u = us[e], v = vs[e];
        int s1 = atomicAdd(&g_cnt[u], 1);
        if (s1 < MAXD) g_adj[u * MAXD + s1] = (e << 12) | v;
        if (u != v) {
            int s2 = atomicAdd(&g_cnt[v], 1);
            if (s2 < MAXD) g_adj[v * MAXD + s2] = (e << 12) | u;
        }
    }

    // per-node: a, c, avt, avu, p0, pdot0   (warp per node)
    for (int n = wid; n < Nn; n += NW) {
        float v0 = vf[n*ND+lane], v1 = vf[n*ND+lane+32], v2 = vf[n*ND+lane+64], v3 = vf[n*ND+lane+96];
        float sa = warp_sum(v0*We[lane]     + v1*We[lane+32]     + v2*We[lane+64]     + v3*We[lane+96]);
        float sc = warp_sum(v0*We[192+lane] + v1*We[192+lane+32] + v2*We[192+lane+64] + v3*We[192+lane+96]);
        float st = warp_sum(v0*Wt[lane]     + v1*Wt[lane+32]     + v2*Wt[lane+64]     + v3*Wt[lane+96]);
        float su = warp_sum(v0*Wu[lane]     + v1*Wu[lane+32]     + v2*Wu[lane+64]     + v3*Wu[lane+96]);
        float pk = 0.f;
#pragma unroll
        for (int k = 0; k < PQ; k++) {
            float s = warp_sum(v0*Wp[lane*PQ+k] + v1*Wp[(lane+32)*PQ+k] +
                               v2*Wp[(lane+64)*PQ+k] + v3*Wp[(lane+96)*PQ+k]);
            if (lane == k) pk = tanhf(s + bp[k]);
        }
        float pd = warp_sum(lane < PQ ? pk * wt2[lane] : 0.f);
        if (lane < PQ) { g_p[n*PQ+lane] = pk; g_psum[n*PQ+lane] = pk; }
        if (lane == 0) { g_a[n] = sa; g_c[n] = sc; g_avt[n] = st; g_avu[n] = su; g_pdot[n] = pd; }
    }
    gsync();  // 1

    // ================= P1: edge weights =================
    for (int e = wid; e < Ee; e += NW) {
        float s = ef[e*ED+lane] * We[128+lane] + ef[e*ED+32+lane] * We[160+lane];
        s = warp_sum(s);
        if (lane == 0) {
            int u = us[e], v = vs[e];
            g_w[e] = sigmoidf(g_a[u] + g_c[v] + s + be[0]);
        }
    }
    gsync();  // 2

    // ================= P2: q0 = tanh((e@v)@Wq+bq), qdot0 (warp per node) =================
    for (int n = wid; n < Nn; n += NW) {
        int deg = min(g_cnt[n], MAXD);
        float x0 = vf[n*ND+lane], x1 = vf[n*ND+lane+32], x2 = vf[n*ND+lane+64], x3 = vf[n*ND+lane+96];
        float e0 = 0.f, e1 = 0.f, e2 = 0.f, e3 = 0.f;
        for (int j = 0; j < deg; j++) {
            int val = g_adj[n*MAXD + j];
            int o = val & 0xFFF;
            float w = g_w[val >> 12];
            if (o == n) { e0 += w*x0; e1 += w*x1; e2 += w*x2; e3 += w*x3; }
            else {
                e0 += w * (x0 + vf[o*ND+lane]);
                e1 += w * (x1 + vf[o*ND+lane+32]);
                e2 += w * (x2 + vf[o*ND+lane+64]);
                e3 += w * (x3 + vf[o*ND+lane+96]);
            }
        }
        float qk = 0.f;
#pragma unroll
        for (int k = 0; k < PQ; k++) {
            float s = warp_sum(e0*Wq[lane*PQ+k] + e1*Wq[(lane+32)*PQ+k] +
                               e2*Wq[(lane+64)*PQ+k] + e3*Wq[(lane+96)*PQ+k]);
            if (lane == k) qk = tanhf(s + bq[k]);
        }
        float qd = warp_sum(lane < PQ ? qk * wu2[lane] : 0.f);
        if (lane < PQ) { g_q[n*PQ+lane] = qk; g_qsum[n*PQ+lane] = qk; }
        if (lane == 0) g_qdot[n] = qd;
    }
    gsync();  // 3

    // ================= layers =================
    for (int i = 0; i < LAYERS; i++) {
        // ---- P_a: su, st (thread per node); block0/warp0: finish layer i-1 c-loss ----
        if (b == 0 && i > 0 && tid < 32) {
            float term = 0.f;
            for (int m = tid; m < Mm; m += 32) {
                float Gm = g_Gm[m], Sm = g_Sm[m];
                term += Gm*Gm*nWu + 2.f*FRIC*Gm*Sm*dTU + FRIC*FRIC*Sm*Sm*nWt;
                g_Gm[m] = 0.f; g_Sm[m] = 0.f;
            }
            term = warp_sum(term);
            if (tid == 0) g_cTot += TAU * sqrtf(term);
        }
        if (gtid < Nn) {
            int n = gtid;
            int deg = min(g_cnt[n], MAXD);
            float qdn = g_qdot[n];
            float s = 0.f;
            for (int j = 0; j < deg; j++) {
                int val = g_adj[n*MAXD + j];
                int o = val & 0xFFF;
                float w = g_w[val >> 12];
                s += (o == n) ? w * qdn : w * (qdn + g_qdot[o]);
            }
            float zu = g_avu[n] + s;
            float zt = g_avt[n] + g_pdot[n];
            float su = sigmoidf(zu), st = sigmoidf(zt);
            g_su[n] = su; g_st[n] = st;
            if (i == LAYERS - 1) {
                int m = g_mol[n];
                atomicAdd(&g_h[m], softplusf(zt) + softplusf(zu));
                atomicAdd(&g_d[m], st * st);
            }
        }
        gsync();

        // ---- P_b: g gather, p/q update, losses (thread per node) ----
        if (gtid < Nn) {
            int n = gtid;
            int deg = min(g_cnt[n], MAXD);
            float sun = g_su[n];
            float g = 0.f;
            for (int j = 0; j < deg; j++) {
                int val = g_adj[n*MAXD + j];
                int o = val & 0xFFF;
                float w = g_w[val >> 12];
                g += (o == n) ? w * sun : w * (sun + g_su[o]);
            }
            float st = g_st[n];
            float d2 = 0.f, pd = 0.f, qd = 0.f;
#pragma unroll
            for (int k = 0; k < PQ; k++) {
                float gp = st * wt2[k];
                float gq = g  * wu2[k];
                float dq = gp;
                float dp = -gq - FRIC * gp;
                float po = g_p[n*PQ+k], qo = g_q[n*PQ+k];
                float diff = dq - po; d2 += diff * diff;
                float pn = po + TAU * dp, qn = qo + TAU * dq;
                g_p[n*PQ+k] = pn; g_q[n*PQ+k] = qn;
                g_psum[n*PQ+k] += pn; g_qsum[n*PQ+k] += qn;
                pd += pn * wt2[k]; qd += qn * wu2[k];
            }
            g_pdot[n] = pd; g_qdot[n] = qd;
            int m = g_mol[n];
            atomicAdd(&g_Gm[m], g);
            atomicAdd(&g_Sm[m], st);
            d2 = warp_sum(d2);
            if (lane == 0) atomicAdd(&g_S[i], d2);
        }
        gsync();
    }

    // ================= final: outputs + cnt reset =================
    for (int idx = gtid; idx < 2 * Nn * PQ; idx += NT)
        out[idx] = (idx < Nn*PQ ? g_psum[idx] : g_qsum[idx - Nn*PQ]) * 0.2f;

    if (b == 0 && tid < 32) {
        float term = 0.f;
        for (int m = tid; m < Mm; m += 32) {
            float Gm = g_Gm[m], Sm = g_Sm[m];
            term += Gm*Gm*nWu + 2.f*FRIC*Gm*Sm*dTU + FRIC*FRIC*Sm*Sm*nWt;
            out[2*Nn*PQ + 2 + m]      = g_h[m];
            out[2*Nn*PQ + 2 + Mm + m] = g_d[m] * nWt;
        }
        term = warp_sum(term);
        if (tid == 0) {
            float cT = g_cTot + TAU * sqrtf(term);
            float sT = 0.f;
#pragma unroll
            for (int l = 0; l < LAYERS; l++) sT += sqrtf(g_S[l]);
            out[2*Nn*PQ + 0] = sT;
            out[2*Nn*PQ + 1] = cT;
        }
    }
    for (int idx = gtid; idx < Nn; idx += NT) g_cnt[idx] = 0;
}

extern "C" void kernel_launch(void* const* d_in, const int* in_sizes, int n_in,
                              void* d_out, int out_size)
{
    const float* vf  = (const float*)d_in[0];
    const float* ef  = (const float*)d_in[1];
    const int*   us  = (const int*)  d_in[2];
    const int*   vs  = (const int*)  d_in[3];
    const float* mnm = (const float*)d_in[4];
    // d_in[5] mol_node_mask, d_in[6] node_edge_matrix, d_in[7] node_edge_mask: unused
    const float* We  = (const float*)d_in[8];
    const float* be  = (const float*)d_in[9];
    const float* Wp  = (const float*)d_in[10];
    const float* bp  = (const float*)d_in[11];
    const float* Wq  = (const float*)d_in[12];
    const float* bq  = (const float*)d_in[13];
    const float* Wt  = (const float*)d_in[14];
    const float* Wu  = (const float*)d_in[15];
    float* out = (float*)d_out;

    fused_kernel<<<NB, BT>>>(vf, ef, us, vs, mnm, We, be, Wp, bp, Wq, bq, Wt, Wu, out);
}

// round 4
// speedup vs baseline: 1.3514x; 1.3514x over previous
#include <cuda_runtime.h>
#include <math.h>

#define Nn 4096
#define Ee 8192
#define Mm 128
#define ND 128
#define ED 64
#define PQ 16
#define NP (Nn*PQ)
#define LAYERS 4
#define TAU 0.25f
#define FRIC 0.1f
#define MAXD 32
#define INC_CAP 16384

// ---------------- device scratch (no allocation allowed) ----------------
__device__ float g_a[Nn], g_c[Nn], g_avt[Nn], g_avu[Nn];
__device__ float g_pd0[Nn], g_pwu[Nn], g_pn[Nn], g_qd0[Nn], g_Wn[Nn];
__device__ int   g_mol[Nn];
__device__ int   g_cnt[Nn];            // must be zero at k1 entry; reset in k5
__device__ int   g_adj[Nn * MAXD];     // (e<<12)|other
__device__ float g_winc[Nn * MAXD];    // per-slot edge weight
__device__ int   g_slotU[Ee], g_slotV[Ee];
__device__ float g_p0[NP], g_q0[NP];
__device__ float g_SA[Nn], g_SB[Nn], g_SC[Nn];

__device__ __forceinline__ float warp_sum(float v) {
#pragma unroll
    for (int o = 16; o; o >>= 1) v += __shfl_xor_sync(0xffffffffu, v, o);
    return v;
}
__device__ __forceinline__ float sigmoidf(float x) { return 1.f / (1.f + expf(-x)); }
__device__ __forceinline__ float softplusf(float x) { return fmaxf(x, 0.f) + log1pf(expf(-fabsf(x))); }

// ======== k1: node setup (warp/node) + mol ids + adjacency build ========
__global__ void k1(const float* __restrict__ vf, const float* __restrict__ mnm,
                   const int* __restrict__ us, const int* __restrict__ vs,
                   const float* __restrict__ We, const float* __restrict__ Wp,
                   const float* __restrict__ bp, const float* __restrict__ Wt,
                   const float* __restrict__ Wu)
{
    int tid  = blockIdx.x * blockDim.x + threadIdx.x;   // 131072 threads
    int lane = threadIdx.x & 31;
    int n    = tid >> 5;                                 // warp -> node

    if (tid < Nn) g_Wn[tid] = 0.f;

    // molecule ids: coalesced sweep of mnm [Mm, Nn]
    for (int idx = tid; idx < Mm * Nn; idx += 131072)
        if (mnm[idx] > 0.5f) g_mol[idx & (Nn - 1)] = idx >> 12;

    // adjacency build (only first Ee threads iterate)
    for (int e = tid; e < Ee; e += 131072) {
        int u = us[e], v = vs[e];
        int s1 = atomicAdd(&g_cnt[u], 1);
        if (s1 < MAXD) g_adj[u * MAXD + s1] = (e << 12) | v;
        g_slotU[e] = s1;
        if (u != v) {
            int s2 = atomicAdd(&g_cnt[v], 1);
            if (s2 < MAXD) g_adj[v * MAXD + s2] = (e << 12) | u;
            g_slotV[e] = s2;
        }
    }

    // per-node dots + p0
    float v0 = vf[n*ND+lane], v1 = vf[n*ND+lane+32], v2 = vf[n*ND+lane+64], v3 = vf[n*ND+lane+96];
    float sa = warp_sum(v0*We[lane]     + v1*We[lane+32]     + v2*We[lane+64]     + v3*We[lane+96]);
    float sc = warp_sum(v0*We[192+lane] + v1*We[192+lane+32] + v2*We[192+lane+64] + v3*We[192+lane+96]);
    float st = warp_sum(v0*Wt[lane]     + v1*Wt[lane+32]     + v2*Wt[lane+64]     + v3*Wt[lane+96]);
    float su = warp_sum(v0*Wu[lane]     + v1*Wu[lane+32]     + v2*Wu[lane+64]     + v3*Wu[lane+96]);

    float pk = 0.f;
#pragma unroll
    for (int k = 0; k < PQ; k++) {
        float s = warp_sum(v0*Wp[lane*PQ+k] + v1*Wp[(lane+32)*PQ+k] +
                           v2*Wp[(lane+64)*PQ+k] + v3*Wp[(lane+96)*PQ+k]);
        if (lane == k) pk = tanhf(s + bp[k]);
    }
    float pd0 = warp_sum(lane < PQ ? pk * Wt[ND+lane] : 0.f);
    float pwu = warp_sum(lane < PQ ? pk * Wu[ND+lane] : 0.f);
    float pn  = warp_sum(lane < PQ ? pk * pk          : 0.f);
    if (lane < PQ) g_p0[n*PQ+lane] = pk;
    if (lane == 0) {
        g_a[n] = sa; g_c[n] = sc; g_avt[n] = st; g_avu[n] = su;
        g_pd0[n] = pd0; g_pwu[n] = pwu; g_pn[n] = pn;
    }
}

// ======== k2: edge weights (warp/edge) ========
__global__ void k2(const float* __restrict__ ef,
                   const int* __restrict__ us, const int* __restrict__ vs,
                   const float* __restrict__ We, const float* __restrict__ be)
{
    int e    = (blockIdx.x * blockDim.x + threadIdx.x) >> 5;  // 8192 warps
    int lane = threadIdx.x & 31;
    if (e >= Ee) return;
    float s = ef[e*ED+lane] * We[128+lane] + ef[e*ED+32+lane] * We[160+lane];
    s = warp_sum(s);
    if (lane == 0) {
        int u = us[e], v = vs[e];
        float w = sigmoidf(g_a[u] + g_c[v] + s + be[0]);
        int s1 = g_slotU[e];
        if (s1 < MAXD) g_winc[u * MAXD + s1] = w;
        if (u != v) {
            int s2 = g_slotV[e];
            if (s2 < MAXD) g_winc[v * MAXD + s2] = w;
            atomicAdd(&g_Wn[u], w);   // self-loops excluded from Wn:
            atomicAdd(&g_Wn[v], w);   // their slot term supplies w*x_n once
        }
    }
}

// ======== k3: q0 = tanh((e@v)@Wq + bq), qdot0 (warp/node) ========
__global__ void k3(const float* __restrict__ vf, const float* __restrict__ Wq,
                   const float* __restrict__ bq, const float* __restrict__ Wu)
{
    int n    = (blockIdx.x * blockDim.x + threadIdx.x) >> 5;  // 4096 warps
    int lane = threadIdx.x & 31;
    float x0 = vf[n*ND+lane], x1 = vf[n*ND+lane+32], x2 = vf[n*ND+lane+64], x3 = vf[n*ND+lane+96];
    float Wn = g_Wn[n];
    float e0 = Wn*x0, e1 = Wn*x1, e2 = Wn*x2, e3 = Wn*x3;
    int deg = min(g_cnt[n], MAXD);
    for (int j = 0; j < deg; j++) {
        int   o = g_adj[n*MAXD+j] & 0xFFF;
        float w = g_winc[n*MAXD+j];
        e0 += w * vf[o*ND+lane];
        e1 += w * vf[o*ND+lane+32];
        e2 += w * vf[o*ND+lane+64];
        e3 += w * vf[o*ND+lane+96];
    }
    float qk = 0.f;
#pragma unroll
    for (int k = 0; k < PQ; k++) {
        float s = warp_sum(e0*Wq[lane*PQ+k] + e1*Wq[(lane+32)*PQ+k] +
                           e2*Wq[(lane+64)*PQ+k] + e3*Wq[(lane+96)*PQ+k]);
        if (lane == k) qk = tanhf(s + bq[k]);
    }
    float qd0 = warp_sum(lane < PQ ? qk * Wu[ND+lane] : 0.f);
    if (lane < PQ) g_q0[n*PQ+lane] = qk;
    if (lane == 0) g_qd0[n] = qd0;
}

// ======== k4: all 4 layers on scalar state, single block, SMEM-resident ========
#define K4_SMEM 156672
__global__ void __launch_bounds__(1024, 1)
k4(const float* __restrict__ Wt, const float* __restrict__ Wu, float* __restrict__ out)
{
    extern __shared__ char sm_raw[];
    float* s_qdA = (float*)sm_raw;                         // Nn
    float* s_qdB = s_qdA + Nn;                             // Nn
    float* s_su  = s_qdB + Nn;                             // Nn
    float* s_w   = s_su + Nn;                              // INC_CAP
    unsigned short* s_o = (unsigned short*)(s_w + INC_CAP);// INC_CAP (32KB)
    float* s_Gm  = (float*)(s_o + INC_CAP);                // 4*128
    float* s_Sm  = s_Gm + 4*Mm;                            // 4*128
    float* s_h   = s_Sm + 4*Mm;                            // 128
    float* s_d2  = s_h + Mm;                               // 128
    float* s_red = s_d2 + Mm;                              // 64
    int*   s_ib  = (int*)(s_red + 64);                     // 32

    int t = threadIdx.x, lane = t & 31, wp = t >> 5;

    float nWt = 0.f, nWu = 0.f, dTU = 0.f;
#pragma unroll
    for (int k = 0; k < PQ; k++) {
        float a = Wu[ND+k], b = Wt[ND+k];
        nWu += a*a; nWt += b*b; dTU += a*b;
    }

    for (int i = t; i < 4*Mm; i += 1024) { s_Gm[i] = 0.f; s_Sm[i] = 0.f; }
    if (t < Mm) { s_h[t] = 0.f; s_d2[t] = 0.f; }

    int deg[4], off[4], mol[4];
    float Wn[4], qd[4], pd[4];
    float a4[4] = {0,0,0,0}, b4[4] = {0,0,0,0}, c4[4] = {0,0,0,0};
    float SA[4] = {0,0,0,0}, SB[4] = {0,0,0,0}, SC[4] = {0,0,0,0};

    int tot = 0;
#pragma unroll
    for (int j = 0; j < 4; j++) {
        int n = t + j*1024;
        deg[j] = min(g_cnt[n], MAXD);
        tot += deg[j];
    }
    // block-wide exclusive scan of per-thread incidence counts
    int pre = tot;
#pragma unroll
    for (int o = 1; o < 32; o <<= 1) { int v = __shfl_up_sync(0xffffffffu, pre, o); if (lane >= o) pre += v; }
    if (lane == 31) s_ib[wp] = pre;
    __syncthreads();
    if (wp == 0) {
        int v = s_ib[lane], p2 = v;
#pragma unroll
        for (int o = 1; o < 32; o <<= 1) { int x = __shfl_up_sync(0xffffffffu, p2, o); if (lane >= o) p2 += x; }
        s_ib[lane] = p2 - v;
    }
    __syncthreads();
    int base = s_ib[wp] + (pre - tot);
#pragma unroll
    for (int j = 0; j < 4; j++) { off[j] = base; base += deg[j]; }

    // compact incidences into SMEM; load node state
#pragma unroll
    for (int j = 0; j < 4; j++) {
        int n = t + j*1024;
        Wn[j] = g_Wn[n]; qd[j] = g_qd0[n]; pd[j] = g_pd0[n]; mol[j] = g_mol[n];
        s_qdA[n] = qd[j];
        for (int i = 0; i < deg[j]; i++) {
            s_o[off[j]+i] = (unsigned short)(g_adj[n*MAXD+i] & 0xFFF);
            s_w[off[j]+i] = g_winc[n*MAXD+i];
        }
    }
    __syncthreads();

    float slr[LAYERS];
    float* cur = s_qdA;
    float* nxt = s_qdB;
    for (int i = 0; i < LAYERS; i++) {
        float st_[4], su_[4], zt_[4], zu_[4];
#pragma unroll
        for (int j = 0; j < 4; j++) {
            int n = t + j*1024;
            float sg = Wn[j] * qd[j];
            for (int x = off[j]; x < off[j]+deg[j]; x++) sg += s_w[x] * cur[s_o[x]];
            zu_[j] = g_avu[n] + sg;   su_[j] = sigmoidf(zu_[j]);
            zt_[j] = g_avt[n] + pd[j]; st_[j] = sigmoidf(zt_[j]);
            s_su[n] = su_[j];
        }
        __syncthreads();
        float slp = 0.f;
#pragma unroll
        for (int j = 0; j < 4; j++) {
            int n = t + j*1024;
            float gg = Wn[j] * su_[j];
            for (int x = off[j]; x < off[j]+deg[j]; x++) gg += s_w[x] * s_su[s_o[x]];
            // s-loss: || st*Wt2 - p_i ||^2 with p_i = p0 + a*Wt2 + b*Wu2
            float alpha = st_[j] - a4[j], beta = -b4[j];
            slp += alpha*alpha*nWt + beta*beta*nWu + 2.f*alpha*beta*dTU
                 - 2.f*alpha*g_pd0[n] - 2.f*beta*g_pwu[n] + g_pn[n];
            atomicAdd(&s_Gm[i*Mm + mol[j]], gg);
            atomicAdd(&s_Sm[i*Mm + mol[j]], st_[j]);
            if (i == LAYERS-1) {
                atomicAdd(&s_h[mol[j]], softplusf(zt_[j]) + softplusf(zu_[j]));
                atomicAdd(&s_d2[mol[j]], st_[j]*st_[j]);
            }
            a4[j] -= TAU*FRIC*st_[j];
            b4[j] -= TAU*gg;
            c4[j] += TAU*st_[j];
            SA[j] += a4[j]; SB[j] += b4[j]; SC[j] += c4[j];
            pd[j] -= TAU*(gg*dTU + FRIC*st_[j]*nWt);
            qd[j] += TAU*st_[j]*dTU;
            nxt[n] = qd[j];
        }
        slr[i] = slp;
        __syncthreads();
        float* tmp = cur; cur = nxt; nxt = tmp;
    }

    // write final-average coefficients
#pragma unroll
    for (int j = 0; j < 4; j++) {
        int n = t + j*1024;
        g_SA[n] = SA[j]; g_SB[n] = SB[j]; g_SC[n] = SC[j];
    }

    // reduce s-losses per layer
    for (int i = 0; i < LAYERS; i++) {
        float r = warp_sum(slr[i]);
        if (lane == 0) s_red[wp] = r;
        __syncthreads();
        if (wp == 0) {
            float v = warp_sum(s_red[lane]);
            if (lane == 0) s_red[32 + i] = v;
        }
        __syncthreads();
    }

    if (t < 32) {
        float cT = 0.f;
        for (int i = 0; i < LAYERS; i++) {
            float term = 0.f;
            for (int m = lane; m < Mm; m += 32) {
                float Gm = s_Gm[i*Mm+m], Sm = s_Sm[i*Mm+m];
                term += Gm*Gm*nWu + 2.f*FRIC*Gm*Sm*dTU + FRIC*FRIC*Sm*Sm*nWt;
            }
            term = warp_sum(term);
            cT += TAU * sqrtf(term);
        }
        if (lane == 0) {
            float sT = 0.f;
            for (int i = 0; i < LAYERS; i++) sT += sqrtf(s_red[32+i]);
            out[2*NP + 0] = sT;
            out[2*NP + 1] = cT;
        }
    }
    if (t < Mm) {
        out[2*NP + 2 + t]      = s_h[t];
        out[2*NP + 2 + Mm + t] = s_d2[t] * nWt;
    }
}

// ======== k5: expand outputs, reset counters ========
__global__ void k5(const float* __restrict__ Wt, const float* __restrict__ Wu,
                   float* __restrict__ out)
{
    int idx = blockIdx.x * blockDim.x + threadIdx.x;  // 131072 = 2*NP
    if (idx < NP) {
        int n = idx >> 4, k = idx & 15;
        out[idx] = 0.2f * (5.f*g_p0[idx] + g_SA[n]*Wt[ND+k] + g_SB[n]*Wu[ND+k]);
    } else {
        int id2 = idx - NP, n = id2 >> 4, k = id2 & 15;
        out[idx] = 0.2f * (5.f*g_q0[id2] + g_SC[n]*Wt[ND+k]);
    }
    if (idx < Nn) g_cnt[idx] = 0;
}

extern "C" void kernel_launch(void* const* d_in, const int* in_sizes, int n_in,
                              void* d_out, int out_size)
{
    const float* vf  = (const float*)d_in[0];
    const float* ef  = (const float*)d_in[1];
    const int*   us  = (const int*)  d_in[2];
    const int*   vs  = (const int*)  d_in[3];
    const float* mnm = (const float*)d_in[4];
    const float* We  = (const float*)d_in[8];
    const float* be  = (const float*)d_in[9];
    const float* Wp  = (const float*)d_in[10];
    const float* bp  = (const float*)d_in[11];
    const float* Wq  = (const float*)d_in[12];
    const float* bq  = (const float*)d_in[13];
    const float* Wt  = (const float*)d_in[14];
    const float* Wu  = (const float*)d_in[15];
    float* out = (float*)d_out;

    cudaFuncSetAttribute(k4, cudaFuncAttributeMaxDynamicSharedMemorySize, K4_SMEM);

    k1<<<512, 256>>>(vf, mnm, us, vs, We, Wp, bp, Wt, Wu);
    k2<<<1024, 256>>>(ef, us, vs, We, be);
    k3<<<512, 256>>>(vf, Wq, bq, Wu);
    k4<<<1, 1024, K4_SMEM>>>(Wt, Wu, out);
    k5<<<512, 256>>>(Wt, Wu, out);
}